// round 14
// baseline (speedup 1.0000x reference)
#include <cuda_runtime.h>
#include <cstdint>

// ---------------- problem constants ----------------
#define BB        64
#define T_IN      127
#define HOP       256
#define T_OUT     62
#define KEEP_EVEN 16608
#define L_OUT     16670
#define SIG_LD    16672
#define TAIL      62
#define M1P       8192         // padded rows for GEMM1 (B*T_IN = 8128)
#define M2        3968         // B*T_OUT = 31*128

// ---------------- persistent device scratch (zero-init at load) ----------------
__device__ float d_cos[1022];
__device__ float d_sin[1022];
__device__ float d_hann[1022];
__device__ float d_denom[256];
__device__ float d_synth[1022];
__device__ float d_A1[M1P * 512];     // folded [Ref(256) | Imf(256)]; pad rows stay 0
__device__ float d_B1c[256 * 256];    // [k][j] cos((2kj)%1022)
__device__ float d_B1s[256 * 256];    // [k][j] sin((2kj)%1022)
__device__ float d_F[M1P * 512];      // u | v
__device__ float d_tailv[BB * TAIL];
__device__ float d_sig[BB * SIG_LD];
__device__ float d_A2[M2 * 1024];     // [Ee | Eo | Oe | Oo] per row
__device__ float d_B2[4 * 256 * 256]; // [z][m'][k]: z=0 ce, 1 co, 2 se, 3 so

// ---------------- f32x2 helpers ----------------
__device__ __forceinline__ unsigned long long pk2(float x, float y) {
    unsigned long long r;
    asm("mov.b64 %0, {%1,%2};" : "=l"(r) : "f"(x), "f"(y));
    return r;
}
__device__ __forceinline__ unsigned long long dup2(float x) {
    unsigned long long r;
    asm("mov.b64 %0, {%1,%1};" : "=l"(r) : "f"(x));
    return r;
}
__device__ __forceinline__ float2 unpk2(unsigned long long v) {
    float2 f;
    asm("mov.b64 {%0,%1}, %2;" : "=f"(f.x), "=f"(f.y) : "l"(v));
    return f;
}
#define FMA2(acc, a, b) asm("fma.rn.f32x2 %0, %1, %2, %0;" : "+l"(acc) : "l"(a), "l"(b))

// ---------------- init: lut + denom + synth in one block ----------------
__global__ void k_init() {
    int i = threadIdx.x;  // 1024
    if (i < 1022) {
        float s, c;
        sincospif(2.0f * (float)i / 1022.0f, &s, &c);
        d_cos[i] = c; d_sin[i] = s; d_hann[i] = 0.5f - 0.5f * c;
    }
    __syncthreads();
    if (i < 256) {
        float acc = 0.f;
        #pragma unroll
        for (int r = 0; r < 4; r++) {
            int idx = r * 256 + i;
            if (idx < 1022) { float h = d_hann[idx]; acc += h * h; }
        }
        d_denom[i] = acc;
    }
    __syncthreads();
    if (i < 1022) d_synth[i] = d_hann[i] / d_denom[i & 255];
}

// merged fills: blocks 0..255 -> B1 (256x256), blocks 256..511 -> B2 (4x256x256)
__global__ void k_fill() {
    int bid = blockIdx.x;
    if (bid < 256) {
        int idx = bid * 256 + threadIdx.x;   // k*256 + j
        int k = idx >> 8, j = idx & 255;
        int t = (2 * k * j) % 1022;
        d_B1c[idx] = d_cos[t];
        d_B1s[idx] = d_sin[t];
    } else {
        int idx = (bid - 256) * 256 + threadIdx.x;  // m'*256 + k
        int mp = idx >> 8, k = idx & 255;
        int te = (2 * mp * k) % 1022;
        int to = ((2 * mp + 1) * k) % 1022;
        d_B2[idx]             = d_cos[te];
        d_B2[65536 + idx]     = d_cos[to];
        d_B2[2 * 65536 + idx] = -d_sin[te];
        d_B2[3 * 65536 + idx] = -d_sin[to];
    }
}

// input (B,512,T_IN,2) -> folded A1[(b*127+t)][Ref(256)|Imf(256)]
__global__ void k_transpose(const float* __restrict__ in) {
    __shared__ float s0[32][33], s1[32][33], s2[32][33], s3[32][33];
    int b = blockIdx.z;
    int k0 = blockIdx.x * 32, t0 = blockIdx.y * 32;
    int tx = threadIdx.x, ty = threadIdx.y;  // 32x8
    #pragma unroll
    for (int i = 0; i < 4; i++) {
        int kk = ty + i * 8;
        int t = t0 + tx;
        if (t < T_IN) {
            int k = k0 + kk;
            int km = 511 - k;
            float2 vd = ((const float2*)in)[(b * 512 + k) * T_IN + t];
            float2 vm = ((const float2*)in)[(b * 512 + km) * T_IN + t];
            s0[kk][tx] = vd.x; s1[kk][tx] = vd.y;
            s2[kk][tx] = vm.x; s3[kk][tx] = vm.y;
        }
    }
    __syncthreads();
    const float invN = 1.0f / 1022.0f;
    #pragma unroll
    for (int i = 0; i < 4; i++) {
        int tt = ty + i * 8;
        int t = t0 + tt;
        if (t < T_IN) {
            int row = b * T_IN + t;
            int k = k0 + tx;
            float coef = (k == 0) ? invN : 2.0f * invN;
            float ref = coef * (s0[tx][tt] + s2[tx][tt]);
            float imf = (k == 0) ? 0.f : 2.0f * invN * (s1[tx][tt] - s3[tx][tt]);
            d_A1[row * 512 + k]       = ref;
            d_A1[row * 512 + 256 + k] = imf;
        }
    }
}

// frame-126 tail samples (n=960..1021), one block per batch
__global__ void k_tail(const float* __restrict__ in) {
    __shared__ float sRe[512], sIm[512];
    int b = blockIdx.x;
    int tid = threadIdx.x;  // 256
    #pragma unroll
    for (int r = 0; r < 2; r++) {
        int k = tid + r * 256;
        float2 v = ((const float2*)in)[(b * 512 + k) * T_IN + 126];
        sRe[k] = v.x; sIm[k] = v.y;
    }
    __syncthreads();
    int wid = tid >> 5, lane = tid & 31;
    const float invN = 1.0f / 1022.0f;
    for (int d = wid; d < TAIL; d += 8) {
        int n = 960 + d;
        float acc = 0.f;
        for (int k = lane; k < 512; k += 32) {
            int t = (k * n) % 1022;
            float cr = (k == 0 || k == 511) ? invN : 2.f * invN;
            acc += cr * d_cos[t] * sRe[k];
            acc += (-2.f * invN) * d_sin[t] * sIm[k];
        }
        #pragma unroll
        for (int off = 16; off; off >>= 1) acc += __shfl_xor_sync(0xffffffffu, acc, off);
        if (lane == 0) d_tailv[b * TAIL + d] = acc * d_synth[n];
    }
}

// overlap-add (folded u/v) + decimation
__global__ void k_ola() {
    int b = blockIdx.y;
    int j = blockIdx.x * 256 + threadIdx.x;
    if (j >= L_OUT) return;
    float v;
    if (j < KEEP_EVEN) {
        int n = 2 * j;
        int t1 = n >> 8; if (t1 > 126) t1 = 126;
        int t0 = (n > 1020) ? ((n - 765) >> 8) : 0;
        v = 0.f;
        const float* F = d_F + (size_t)b * T_IN * 512;
        for (int t = t0; t <= t1; t++) {
            int o = n - (t << 8);
            const float* Fr = F + (t << 9);
            if (o <= 510) {
                int jj = o >> 1;
                v += d_synth[o] * (Fr[jj] - Fr[256 + jj]);
            } else {
                int jj = (1022 - o) >> 1;
                v += d_synth[o] * (Fr[jj] + Fr[256 + jj]);
            }
        }
    } else {
        v = d_tailv[b * TAIL + (j - KEEP_EVEN)];
    }
    d_sig[b * SIG_LD + j] = v;
}

// windowed even/odd fold + m-parity split -> A2 = [Ee|Eo|Oe|Oo]
__global__ void k_eo() {
    int idx = blockIdx.x * 256 + threadIdx.x;   // r*256 + m'
    int r = idx >> 8, mp = idx & 255;
    int b = r / 62, t = r - b * 62;
    const float* s = d_sig + b * SIG_LD + (t << 8);
    int me = 2 * mp, mo = 2 * mp + 1;
    float ee, eo, oe, oo;
    if (me == 0) { ee = 0.f; oe = 0.f; }
    else {
        float w = d_hann[me];
        float f1 = s[me], f2 = s[1022 - me];
        ee = w * (f1 + f2); oe = w * (f1 - f2);
    }
    if (mo == 511) { eo = d_hann[511] * s[511]; oo = 0.f; }
    else {
        float w = d_hann[mo];
        float f1 = s[mo], f2 = s[1022 - mo];
        eo = w * (f1 + f2); oo = w * (f1 - f2);
    }
    float* A = d_A2 + (size_t)r * 1024 + mp;
    A[0] = ee; A[256] = eo; A[512] = oe; A[768] = oo;
}

// ---------------- GEMM1: f32x2 SGEMM 128x128x16, K=256, occ 2 (R11-proven) ----------------
// z in {0(u),1(v)}: A1[:, z*256:(z+1)*256] @ B1{c,s} -> d_F[:, z*256 + n]
__global__ void __launch_bounds__(256, 2) k_gemm1() {
    __shared__ __align__(16) float As[2][16][132];
    __shared__ __align__(16) float Bs[2][16][128];
    const int tid = threadIdx.x;
    const int tx = tid & 15, ty = tid >> 4;
    const int z = blockIdx.z;
    const int n0 = blockIdx.x << 7;
    const int m0 = blockIdx.y << 7;
    const int arow = tid >> 2;
    const int acol = (tid & 3) << 2;
    const int brow = tid >> 5;
    const int bcol = (tid & 31) << 2;

    const float* __restrict__ Aptr = d_A1 + z * 256;
    const float* __restrict__ Bmat = z ? d_B1s : d_B1c;
    float* __restrict__ Cptr = d_F + z * 256;
    const size_t base0 = (size_t)(m0 + arow) * 512;
    const size_t base1 = (size_t)(m0 + arow + 64) * 512;
    const float* bptr = Bmat + brow * 256 + n0 + bcol;

    float4 ra0 = *(const float4*)(Aptr + base0 + acol);
    float4 ra1 = *(const float4*)(Aptr + base1 + acol);
    float4 rb0 = *(const float4*)(bptr);
    float4 rb1 = *(const float4*)(bptr + 8 * 256);

    As[0][acol + 0][arow] = ra0.x; As[0][acol + 1][arow] = ra0.y;
    As[0][acol + 2][arow] = ra0.z; As[0][acol + 3][arow] = ra0.w;
    As[0][acol + 0][arow + 64] = ra1.x; As[0][acol + 1][arow + 64] = ra1.y;
    As[0][acol + 2][arow + 64] = ra1.z; As[0][acol + 3][arow + 64] = ra1.w;
    *(float4*)&Bs[0][brow][bcol] = rb0;
    *(float4*)&Bs[0][brow + 8][bcol] = rb1;
    __syncthreads();

    unsigned long long acc[4][8];
    #pragma unroll
    for (int p = 0; p < 4; p++)
        #pragma unroll
        for (int q = 0; q < 8; q++) acc[p][q] = 0ull;

    for (int kt = 0; kt < 16; kt++) {
        const int cur = kt & 1;
        if (kt < 15) {
            int ko = (kt + 1) << 4;
            ra0 = *(const float4*)(Aptr + base0 + ko + acol);
            ra1 = *(const float4*)(Aptr + base1 + ko + acol);
            rb0 = *(const float4*)(bptr + ko * 256);
            rb1 = *(const float4*)(bptr + (ko + 8) * 256);
        }
        #pragma unroll
        for (int k = 0; k < 16; k++) {
            float4 a0 = *(const float4*)&As[cur][k][ty << 2];
            float4 a1 = *(const float4*)&As[cur][k][64 + (ty << 2)];
            float4 b0 = *(const float4*)&Bs[cur][k][tx << 2];
            float4 b1 = *(const float4*)&Bs[cur][k][64 + (tx << 2)];
            unsigned long long ap[4] = { pk2(a0.x, a0.y), pk2(a0.z, a0.w),
                                         pk2(a1.x, a1.y), pk2(a1.z, a1.w) };
            unsigned long long bd[8] = { dup2(b0.x), dup2(b0.y), dup2(b0.z), dup2(b0.w),
                                         dup2(b1.x), dup2(b1.y), dup2(b1.z), dup2(b1.w) };
            #pragma unroll
            for (int p = 0; p < 4; p++)
                #pragma unroll
                for (int q = 0; q < 8; q++) FMA2(acc[p][q], ap[p], bd[q]);
        }
        if (kt < 15) {
            const int nb = (kt + 1) & 1;
            As[nb][acol + 0][arow] = ra0.x; As[nb][acol + 1][arow] = ra0.y;
            As[nb][acol + 2][arow] = ra0.z; As[nb][acol + 3][arow] = ra0.w;
            As[nb][acol + 0][arow + 64] = ra1.x; As[nb][acol + 1][arow + 64] = ra1.y;
            As[nb][acol + 2][arow + 64] = ra1.z; As[nb][acol + 3][arow + 64] = ra1.w;
            *(float4*)&Bs[nb][brow][bcol] = rb0;
            *(float4*)&Bs[nb][brow + 8][bcol] = rb1;
        }
        __syncthreads();
    }

    float cc[8][8];
    #pragma unroll
    for (int p = 0; p < 4; p++)
        #pragma unroll
        for (int q = 0; q < 8; q++) {
            float2 f = unpk2(acc[p][q]);
            cc[2 * p][q] = f.x;
            cc[2 * p + 1][q] = f.y;
        }

    #pragma unroll
    for (int ri = 0; ri < 8; ri++) {
        int m = m0 + ((ri >= 4) ? 64 : 0) + (ty << 2) + (ri & 3);
        float* dst = Cptr + (size_t)m * 512 + n0;
        *(float4*)(dst + (tx << 2))      = make_float4(cc[ri][0], cc[ri][1], cc[ri][2], cc[ri][3]);
        *(float4*)(dst + 64 + (tx << 2)) = make_float4(cc[ri][4], cc[ri][5], cc[ri][6], cc[ri][7]);
    }
}

// ---------------- GEMM2 fused, occ 2: 128(M) x 64(N) tiles, dual-z accumulators ----------------
// zp=0: Ce (Ee@ce) & Co (Eo@co) -> Re channel;  zp=1: Se (Oe@se) & So (Oo@so) -> Im channel.
// Per thread: 8 M-rows (f32x2-packed) x 4 N-cols per z; combine epilogue writes output directly.
__global__ void __launch_bounds__(256, 2) k_gemm2f(float* __restrict__ outp) {
    __shared__ __align__(16) float As[2][16][132];
    __shared__ __align__(16) float Bs[2][16][64];
    const int tid = threadIdx.x;
    const int tx = tid & 15, ty = tid >> 4;
    const int n0 = blockIdx.x << 6;       // k-block {0,64,128,192}
    const int m0 = blockIdx.y << 7;       // row block (31)
    const int zp = blockIdx.z;            // 0 -> Re, 1 -> Im
    const int arow = tid >> 2;
    const int acol = (tid & 3) << 2;
    const int brow = tid >> 4;            // 0..15
    const int bcol = (tid & 15) << 2;     // 0..60

    unsigned long long acc[2][4][4];
    #pragma unroll
    for (int zi = 0; zi < 2; zi++)
        #pragma unroll
        for (int p = 0; p < 4; p++)
            #pragma unroll
            for (int q = 0; q < 4; q++) acc[zi][p][q] = 0ull;

    #pragma unroll 1
    for (int zi = 0; zi < 2; zi++) {
        const int z = zp * 2 + zi;
        const float* __restrict__ Aptr = d_A2 + z * 256;
        const float* __restrict__ Bmat = d_B2 + z * 65536;
        const size_t base0 = (size_t)(m0 + arow) * 1024;
        const size_t base1 = (size_t)(m0 + arow + 64) * 1024;
        const float* bptr = Bmat + brow * 256 + n0 + bcol;

        float4 ra0 = *(const float4*)(Aptr + base0 + acol);
        float4 ra1 = *(const float4*)(Aptr + base1 + acol);
        float4 rb0 = *(const float4*)(bptr);

        As[0][acol + 0][arow] = ra0.x; As[0][acol + 1][arow] = ra0.y;
        As[0][acol + 2][arow] = ra0.z; As[0][acol + 3][arow] = ra0.w;
        As[0][acol + 0][arow + 64] = ra1.x; As[0][acol + 1][arow + 64] = ra1.y;
        As[0][acol + 2][arow + 64] = ra1.z; As[0][acol + 3][arow + 64] = ra1.w;
        *(float4*)&Bs[0][brow][bcol] = rb0;
        __syncthreads();

        for (int kt = 0; kt < 16; kt++) {
            const int cur = kt & 1;
            if (kt < 15) {
                int ko = (kt + 1) << 4;
                ra0 = *(const float4*)(Aptr + base0 + ko + acol);
                ra1 = *(const float4*)(Aptr + base1 + ko + acol);
                rb0 = *(const float4*)(bptr + ko * 256);
            }
            #pragma unroll
            for (int k = 0; k < 16; k++) {
                float4 a0 = *(const float4*)&As[cur][k][ty << 2];
                float4 a1 = *(const float4*)&As[cur][k][64 + (ty << 2)];
                float4 b0 = *(const float4*)&Bs[cur][k][tx << 2];
                unsigned long long ap[4] = { pk2(a0.x, a0.y), pk2(a0.z, a0.w),
                                             pk2(a1.x, a1.y), pk2(a1.z, a1.w) };
                unsigned long long bd[4] = { dup2(b0.x), dup2(b0.y), dup2(b0.z), dup2(b0.w) };
                #pragma unroll
                for (int p = 0; p < 4; p++)
                    #pragma unroll
                    for (int q = 0; q < 4; q++) FMA2(acc[zi][p][q], ap[p], bd[q]);
            }
            if (kt < 15) {
                const int nb = (kt + 1) & 1;
                As[nb][acol + 0][arow] = ra0.x; As[nb][acol + 1][arow] = ra0.y;
                As[nb][acol + 2][arow] = ra0.z; As[nb][acol + 3][arow] = ra0.w;
                As[nb][acol + 0][arow + 64] = ra1.x; As[nb][acol + 1][arow + 64] = ra1.y;
                As[nb][acol + 2][arow + 64] = ra1.z; As[nb][acol + 3][arow + 64] = ra1.w;
                *(float4*)&Bs[nb][brow][bcol] = rb0;
            }
            __syncthreads();
        }
    }

    // combine epilogue: v0 = Ce|Se, v1 = Co|So; write Re|Im channel at j=k and j=511-k
    #pragma unroll
    for (int ri = 0; ri < 8; ri++) {
        int m = m0 + ((ri >= 4) ? 64 : 0) + (ty << 2) + (ri & 3);
        int b = m / 62, t = m - b * 62;
        size_t obase = ((size_t)b * 31744 + t) * 2 + zp;   // + j*124
        const int p = ((ri >= 4) ? 2 : 0) + ((ri & 3) >> 1);
        #pragma unroll
        for (int q = 0; q < 4; q++) {
            int k = n0 + (tx << 2) + q;
            float2 f0 = unpk2(acc[0][p][q]);
            float2 f1 = unpk2(acc[1][p][q]);
            float v0 = (ri & 1) ? f0.y : f0.x;
            float v1 = (ri & 1) ? f1.y : f1.x;
            float lo = v0 + v1;
            float hi = zp ? (v1 - v0) : (v0 - v1);
            outp[obase + (size_t)k * 124]         = lo;
            outp[obase + (size_t)(511 - k) * 124] = hi;
        }
    }
}

// ---------------- launch ----------------
extern "C" void kernel_launch(void* const* d_in, const int* in_sizes, int n_in,
                              void* d_out, int out_size) {
    (void)in_sizes; (void)n_in; (void)out_size;
    const float* in = (const float*)d_in[0];
    float* out = (float*)d_out;

    k_init<<<1, 1024>>>();
    k_fill<<<512, 256>>>();
    k_transpose<<<dim3(8, 4, BB), dim3(32, 8)>>>(in);
    k_gemm1<<<dim3(2, 64, 2), 256>>>();
    k_tail<<<BB, 256>>>(in);
    k_ola<<<dim3((L_OUT + 255) / 256, BB), 256>>>();
    k_eo<<<(M2 * 256) / 256, 256>>>();
    k_gemm2f<<<dim3(4, 31, 2), 256>>>(out);
}

// round 17
// speedup vs baseline: 2.0081x; 2.0081x over previous
#include <cuda_runtime.h>
#include <cstdint>

// ---------------- problem constants ----------------
#define BB        64
#define T_IN      127
#define HOP       256
#define T_OUT     62
#define KEEP_EVEN 16608
#define L_OUT     16670
#define SIG_LD    16672
#define TAIL      62
#define M1P       8192         // padded rows for GEMM1 (B*T_IN = 8128)
#define M2        3968         // B*T_OUT = 31*128

// ---------------- persistent device scratch (zero-init at load) ----------------
__device__ float d_cos[1022];
__device__ float d_sin[1022];
__device__ float d_hann[1022];
__device__ float d_synth[1022];
__device__ float d_A1[M1P * 512];     // folded [Ref(256) | Imf(256)]; pad rows stay 0
__device__ float d_B1c[256 * 256];    // [k][j] cos((2kj)%1022)
__device__ float d_B1s[256 * 256];    // [k][j] sin((2kj)%1022)
__device__ float d_F[M1P * 512];      // u | v
__device__ float d_tailv[BB * TAIL];
__device__ float d_sig[BB * SIG_LD];
__device__ float d_A2[M2 * 1024];     // [Ee | Eo | Oe | Oo] per row
__device__ float d_B2[4 * 256 * 256]; // [z][m'][k]: z=0 ce, 1 co, 2 se, 3 so
__device__ float d_C2[M2 * 1024];     // [Ce | Co | Se | So] per row

// ---------------- f32x2 helpers ----------------
__device__ __forceinline__ unsigned long long pk2(float x, float y) {
    unsigned long long r;
    asm("mov.b64 %0, {%1,%2};" : "=l"(r) : "f"(x), "f"(y));
    return r;
}
__device__ __forceinline__ unsigned long long dup2(float x) {
    unsigned long long r;
    asm("mov.b64 %0, {%1,%1};" : "=l"(r) : "f"(x));
    return r;
}
__device__ __forceinline__ float2 unpk2(unsigned long long v) {
    float2 f;
    asm("mov.b64 {%0,%1}, %2;" : "=f"(f.x), "=f"(f.y) : "l"(v));
    return f;
}
#define FMA2(acc, a, b) asm("fma.rn.f32x2 %0, %1, %2, %0;" : "+l"(acc) : "l"(a), "l"(b))

// ---------------- fill + init in one kernel ----------------
// blocks 0..255   -> B1 (256x256): trig computed directly (identical to LUT values)
// blocks 256..511 -> B2 (4x256x256)
// block 512       -> LUT init (cos/sin/hann/synth) for tail/ola/eo
__global__ void k_fill() {
    int bid = blockIdx.x;
    int tid = threadIdx.x;
    if (bid < 256) {
        int idx = bid * 256 + tid;           // k*256 + j
        int k = idx >> 8, j = idx & 255;
        int t = (2 * k * j) % 1022;
        float s, c;
        sincospif(2.0f * (float)t / 1022.0f, &s, &c);
        d_B1c[idx] = c;
        d_B1s[idx] = s;
    } else if (bid < 512) {
        int idx = (bid - 256) * 256 + tid;   // m'*256 + k
        int mp = idx >> 8, k = idx & 255;
        int te = (2 * mp * k) % 1022;
        int to = ((2 * mp + 1) * k) % 1022;
        float se, ce, so, co;
        sincospif(2.0f * (float)te / 1022.0f, &se, &ce);
        sincospif(2.0f * (float)to / 1022.0f, &so, &co);
        d_B2[idx]             = ce;
        d_B2[65536 + idx]     = co;
        d_B2[2 * 65536 + idx] = -se;
        d_B2[3 * 65536 + idx] = -so;
    } else {
        __shared__ float sh[1022];
        #pragma unroll
        for (int r = 0; r < 4; r++) {
            int i = r * 256 + tid;
            if (i < 1022) {
                float s, c;
                sincospif(2.0f * (float)i / 1022.0f, &s, &c);
                d_cos[i] = c; d_sin[i] = s;
                float h = 0.5f - 0.5f * c;
                d_hann[i] = h; sh[i] = h;
            }
        }
        __syncthreads();
        float acc = 0.f;
        #pragma unroll
        for (int r = 0; r < 4; r++) {
            int i = r * 256 + tid;
            if (i < 1022) { float h = sh[i]; acc += h * h; }
        }
        float inv = 1.0f / acc;              // denom[tid & 255]
        __syncthreads();
        #pragma unroll
        for (int r = 0; r < 4; r++) {
            int i = r * 256 + tid;
            if (i < 1022) d_synth[i] = sh[i] * inv;
        }
    }
}

// input (B,512,T_IN,2) -> folded A1[(b*127+t)][Ref(256)|Imf(256)]
// blockIdx.x == 8 plane: frame-126 tail samples (n=960..1021) for batch blockIdx.z
__global__ void k_transpose(const float* __restrict__ in) {
    __shared__ float s0[32][33], s1[32][33], s2[32][33], s3[32][33];
    __shared__ float sRe[512], sIm[512];
    int b = blockIdx.z;
    int tx = threadIdx.x, ty = threadIdx.y;  // 32x8
    if (blockIdx.x == 8) {
        if (blockIdx.y != 0) return;
        int tid = ty * 32 + tx;              // 0..255
        #pragma unroll
        for (int r = 0; r < 2; r++) {
            int k = tid + r * 256;
            float2 v = ((const float2*)in)[(b * 512 + k) * T_IN + 126];
            sRe[k] = v.x; sIm[k] = v.y;
        }
        __syncthreads();
        int wid = tid >> 5, lane = tid & 31;
        const float invN = 1.0f / 1022.0f;
        for (int d = wid; d < TAIL; d += 8) {
            int n = 960 + d;
            float acc = 0.f;
            for (int k = lane; k < 512; k += 32) {
                int t = (k * n) % 1022;
                float cr = (k == 0 || k == 511) ? invN : 2.f * invN;
                acc += cr * d_cos[t] * sRe[k];
                acc += (-2.f * invN) * d_sin[t] * sIm[k];
            }
            #pragma unroll
            for (int off = 16; off; off >>= 1) acc += __shfl_xor_sync(0xffffffffu, acc, off);
            if (lane == 0) d_tailv[b * TAIL + d] = acc * d_synth[n];
        }
        return;
    }
    int k0 = blockIdx.x * 32, t0 = blockIdx.y * 32;
    #pragma unroll
    for (int i = 0; i < 4; i++) {
        int kk = ty + i * 8;
        int t = t0 + tx;
        if (t < T_IN) {
            int k = k0 + kk;
            int km = 511 - k;
            float2 vd = ((const float2*)in)[(b * 512 + k) * T_IN + t];
            float2 vm = ((const float2*)in)[(b * 512 + km) * T_IN + t];
            s0[kk][tx] = vd.x; s1[kk][tx] = vd.y;
            s2[kk][tx] = vm.x; s3[kk][tx] = vm.y;
        }
    }
    __syncthreads();
    const float invN = 1.0f / 1022.0f;
    #pragma unroll
    for (int i = 0; i < 4; i++) {
        int tt = ty + i * 8;
        int t = t0 + tt;
        if (t < T_IN) {
            int row = b * T_IN + t;
            int k = k0 + tx;
            float coef = (k == 0) ? invN : 2.0f * invN;
            float ref = coef * (s0[tx][tt] + s2[tx][tt]);
            float imf = (k == 0) ? 0.f : 2.0f * invN * (s1[tx][tt] - s3[tx][tt]);
            d_A1[row * 512 + k]       = ref;
            d_A1[row * 512 + 256 + k] = imf;
        }
    }
}

// overlap-add (folded u/v) + decimation
__global__ void k_ola() {
    int b = blockIdx.y;
    int j = blockIdx.x * 256 + threadIdx.x;
    if (j >= L_OUT) return;
    float v;
    if (j < KEEP_EVEN) {
        int n = 2 * j;
        int t1 = n >> 8; if (t1 > 126) t1 = 126;
        int t0 = (n > 1020) ? ((n - 765) >> 8) : 0;
        v = 0.f;
        const float* F = d_F + (size_t)b * T_IN * 512;
        for (int t = t0; t <= t1; t++) {
            int o = n - (t << 8);
            const float* Fr = F + (t << 9);
            if (o <= 510) {
                int jj = o >> 1;
                v += d_synth[o] * (Fr[jj] - Fr[256 + jj]);
            } else {
                int jj = (1022 - o) >> 1;
                v += d_synth[o] * (Fr[jj] + Fr[256 + jj]);
            }
        }
    } else {
        v = d_tailv[b * TAIL + (j - KEEP_EVEN)];
    }
    d_sig[b * SIG_LD + j] = v;
}

// windowed even/odd fold + m-parity split -> A2 = [Ee|Eo|Oe|Oo]
__global__ void k_eo() {
    int idx = blockIdx.x * 256 + threadIdx.x;   // r*256 + m'
    int r = idx >> 8, mp = idx & 255;
    int b = r / 62, t = r - b * 62;
    const float* s = d_sig + b * SIG_LD + (t << 8);
    int me = 2 * mp, mo = 2 * mp + 1;
    float ee, eo, oe, oo;
    if (me == 0) { ee = 0.f; oe = 0.f; }
    else {
        float w = d_hann[me];
        float f1 = s[me], f2 = s[1022 - me];
        ee = w * (f1 + f2); oe = w * (f1 - f2);
    }
    if (mo == 511) { eo = d_hann[511] * s[511]; oo = 0.f; }
    else {
        float w = d_hann[mo];
        float f1 = s[mo], f2 = s[1022 - mo];
        eo = w * (f1 + f2); oo = w * (f1 - f2);
    }
    float* A = d_A2 + (size_t)r * 1024 + mp;
    A[0] = ee; A[256] = eo; A[512] = oe; A[768] = oo;
}

// ---------------- f32x2 SGEMM: 128x128x16 tiles, 256 thr, 8x8/thread, K=256 (R11-proven) ----------------
// WHICH==1: z in {0(u),1(v)}: A1[:, z*256:(z+1)*256] @ B1{c,s} -> d_F[:, z*256 + n]
// WHICH==2: z in {0..3}:      A2[:, z*256:...] @ B2[z] -> d_C2[:, z*256 + n]
template <int WHICH>
__global__ void __launch_bounds__(256, 2) k_gemm() {
    __shared__ __align__(16) float As[2][16][132];
    __shared__ __align__(16) float Bs[2][16][128];
    const int tid = threadIdx.x;
    const int tx = tid & 15, ty = tid >> 4;
    const int z = blockIdx.z;
    const int n0 = blockIdx.x << 7;
    const int m0 = blockIdx.y << 7;
    const int arow = tid >> 2;
    const int acol = (tid & 3) << 2;
    const int brow = tid >> 5;
    const int bcol = (tid & 31) << 2;

    const float* __restrict__ Aptr;
    const float* __restrict__ Bmat;
    float* __restrict__ Cptr;
    int lda, ldc;
    if (WHICH == 1) {
        Aptr = d_A1 + z * 256; lda = 512;
        Bmat = z ? d_B1s : d_B1c;
        Cptr = d_F + z * 256;  ldc = 512;
    } else {
        Aptr = d_A2 + z * 256; lda = 1024;
        Bmat = d_B2 + z * 65536;
        Cptr = d_C2 + z * 256; ldc = 1024;
    }
    const size_t base0 = (size_t)(m0 + arow) * lda;
    const size_t base1 = (size_t)(m0 + arow + 64) * lda;
    const float* bptr = Bmat + brow * 256 + n0 + bcol;

    float4 ra0 = *(const float4*)(Aptr + base0 + acol);
    float4 ra1 = *(const float4*)(Aptr + base1 + acol);
    float4 rb0 = *(const float4*)(bptr);
    float4 rb1 = *(const float4*)(bptr + 8 * 256);

    As[0][acol + 0][arow] = ra0.x; As[0][acol + 1][arow] = ra0.y;
    As[0][acol + 2][arow] = ra0.z; As[0][acol + 3][arow] = ra0.w;
    As[0][acol + 0][arow + 64] = ra1.x; As[0][acol + 1][arow + 64] = ra1.y;
    As[0][acol + 2][arow + 64] = ra1.z; As[0][acol + 3][arow + 64] = ra1.w;
    *(float4*)&Bs[0][brow][bcol] = rb0;
    *(float4*)&Bs[0][brow + 8][bcol] = rb1;
    __syncthreads();

    unsigned long long acc[4][8];
    #pragma unroll
    for (int p = 0; p < 4; p++)
        #pragma unroll
        for (int q = 0; q < 8; q++) acc[p][q] = 0ull;

    for (int kt = 0; kt < 16; kt++) {
        const int cur = kt & 1;
        if (kt < 15) {
            int ko = (kt + 1) << 4;
            ra0 = *(const float4*)(Aptr + base0 + ko + acol);
            ra1 = *(const float4*)(Aptr + base1 + ko + acol);
            rb0 = *(const float4*)(bptr + ko * 256);
            rb1 = *(const float4*)(bptr + (ko + 8) * 256);
        }
        #pragma unroll
        for (int k = 0; k < 16; k++) {
            float4 a0 = *(const float4*)&As[cur][k][ty << 2];
            float4 a1 = *(const float4*)&As[cur][k][64 + (ty << 2)];
            float4 b0 = *(const float4*)&Bs[cur][k][tx << 2];
            float4 b1 = *(const float4*)&Bs[cur][k][64 + (tx << 2)];
            unsigned long long ap[4] = { pk2(a0.x, a0.y), pk2(a0.z, a0.w),
                                         pk2(a1.x, a1.y), pk2(a1.z, a1.w) };
            unsigned long long bd[8] = { dup2(b0.x), dup2(b0.y), dup2(b0.z), dup2(b0.w),
                                         dup2(b1.x), dup2(b1.y), dup2(b1.z), dup2(b1.w) };
            #pragma unroll
            for (int p = 0; p < 4; p++)
                #pragma unroll
                for (int q = 0; q < 8; q++) FMA2(acc[p][q], ap[p], bd[q]);
        }
        if (kt < 15) {
            const int nb = (kt + 1) & 1;
            As[nb][acol + 0][arow] = ra0.x; As[nb][acol + 1][arow] = ra0.y;
            As[nb][acol + 2][arow] = ra0.z; As[nb][acol + 3][arow] = ra0.w;
            As[nb][acol + 0][arow + 64] = ra1.x; As[nb][acol + 1][arow + 64] = ra1.y;
            As[nb][acol + 2][arow + 64] = ra1.z; As[nb][acol + 3][arow + 64] = ra1.w;
            *(float4*)&Bs[nb][brow][bcol] = rb0;
            *(float4*)&Bs[nb][brow + 8][bcol] = rb1;
        }
        __syncthreads();
    }

    float cc[8][8];
    #pragma unroll
    for (int p = 0; p < 4; p++)
        #pragma unroll
        for (int q = 0; q < 8; q++) {
            float2 f = unpk2(acc[p][q]);
            cc[2 * p][q] = f.x;
            cc[2 * p + 1][q] = f.y;
        }

    #pragma unroll
    for (int ri = 0; ri < 8; ri++) {
        int m = m0 + ((ri >= 4) ? 64 : 0) + (ty << 2) + (ri & 3);
        float* dst = Cptr + (size_t)m * ldc + n0;
        *(float4*)(dst + (tx << 2))      = make_float4(cc[ri][0], cc[ri][1], cc[ri][2], cc[ri][3]);
        *(float4*)(dst + 64 + (tx << 2)) = make_float4(cc[ri][4], cc[ri][5], cc[ri][6], cc[ri][7]);
    }
}

// combine Ce/Co/Se/So -> output (B,512,T_OUT,2), float2-vectorized channel stores
__global__ void k_combine(float* __restrict__ outp) {
    int idx = blockIdx.x * 256 + threadIdx.x;   // r*256 + k
    int r = idx >> 8, k = idx & 255;
    const float* C = d_C2 + (size_t)r * 1024 + k;
    float ce = C[0], co = C[256], se = C[512], so = C[768];
    int b = r / 62, t = r - b * 62;
    int jlo = k, jhi = 511 - k;
    size_t olo = ((size_t)((b << 9) + jlo) * 62 + t) * 2;
    size_t ohi = ((size_t)((b << 9) + jhi) * 62 + t) * 2;
    *(float2*)(outp + olo) = make_float2(ce + co, se + so);
    *(float2*)(outp + ohi) = make_float2(ce - co, so - se);
}

// ---------------- launch ----------------
extern "C" void kernel_launch(void* const* d_in, const int* in_sizes, int n_in,
                              void* d_out, int out_size) {
    (void)in_sizes; (void)n_in; (void)out_size;
    const float* in = (const float*)d_in[0];
    float* out = (float*)d_out;

    k_fill<<<513, 256>>>();
    k_transpose<<<dim3(9, 4, BB), dim3(32, 8)>>>(in);
    k_gemm<1><<<dim3(2, 64, 2), 256>>>();
    k_ola<<<dim3((L_OUT + 255) / 256, BB), 256>>>();
    k_eo<<<(M2 * 256) / 256, 256>>>();
    k_gemm<2><<<dim3(2, 31, 4), 256>>>();
    k_combine<<<(M2 * 256) / 256, 256>>>(out);
}